// round 1
// baseline (speedup 1.0000x reference)
#include <cuda_runtime.h>
#include <cuda_fp16.h>
#include <math.h>
#include <stdint.h>

// SoftmaxAttention: B=4,H=16,S=2048,D=64 fp32.
// Flash-attention, fp16 mma.sync (m16n8k16) with fp32 accumulation.

#define DH 64
#define BM 128
#define BN 64
#define NWARP 8
#define NTHREADS 256
#define KSTRIDE (DH + 8)   // halfs per K row (pad 8 -> conflict-free frag loads)
#define VSTRIDE (DH + 8)   // half2 per V-pair row (pad 8 -> conflict-free frag loads)

__device__ __forceinline__ uint32_t h2bits(__half2 h) {
    return *reinterpret_cast<uint32_t*>(&h);
}

__device__ __forceinline__ void mma16816(float c[4], const uint32_t a[4],
                                         uint32_t b0, uint32_t b1) {
    asm volatile(
        "mma.sync.aligned.m16n8k16.row.col.f32.f16.f16.f32 "
        "{%0,%1,%2,%3}, {%4,%5,%6,%7}, {%8,%9}, {%0,%1,%2,%3};\n"
        : "+f"(c[0]), "+f"(c[1]), "+f"(c[2]), "+f"(c[3])
        : "r"(a[0]), "r"(a[1]), "r"(a[2]), "r"(a[3]), "r"(b0), "r"(b1));
}

__global__ __launch_bounds__(NTHREADS, 2)
void attn_flash_f16(const float* __restrict__ Q, const float* __restrict__ K,
                    const float* __restrict__ V, const float* __restrict__ Mk,
                    float* __restrict__ O, int Hn, int Sn)
{
    __shared__ __half  sK[BN * KSTRIDE];          // [key][d], fp16
    __shared__ __half2 sV[(BN / 2) * VSTRIDE];    // [key_pair][d] = {V[2k][d], V[2k+1][d]}
    __shared__ float   sAM[BN];                   // additive mask per key

    const int tid  = threadIdx.x;
    const int warp = tid >> 5;
    const int lane = tid & 31;
    const int g    = lane >> 2;        // group id (row within m-tile)
    const int m4   = lane & 3;
    const int t2   = m4 * 2;           // col pair base
    const int bh   = blockIdx.y;
    const int bb   = bh / Hn;          // batch index (for mask)
    const long hbase = (long)bh * Sn * DH;
    const int qrow0  = blockIdx.x * BM + warp * 16;

    // ---- Q fragments (persistent in registers), scaled by 1/sqrt(D) = 0.125 ----
    uint32_t qa[4][4];
    #pragma unroll
    for (int kc = 0; kc < 4; kc++) {
        #pragma unroll
        for (int i = 0; i < 4; i++) {
            int row = qrow0 + g + ((i & 1) ? 8 : 0);
            int col = kc * 16 + t2 + ((i & 2) ? 8 : 0);
            float2 qv = *reinterpret_cast<const float2*>(&Q[hbase + (long)row * DH + col]);
            qa[kc][i] = h2bits(__floats2half2_rn(qv.x * 0.125f, qv.y * 0.125f));
        }
    }

    float oacc[8][4];
    #pragma unroll
    for (int dn = 0; dn < 8; dn++)
        #pragma unroll
        for (int j = 0; j < 4; j++) oacc[dn][j] = 0.0f;
    float m1 = -INFINITY, m2 = -INFINITY, l1 = 0.0f, l2 = 0.0f;

    const int nkb = Sn / BN;
    for (int kb = 0; kb < nkb; kb++) {
        __syncthreads();  // previous iteration's smem reads complete

        // ---- stage K tile: fp32 gmem -> fp16 smem [64][72] ----
        {
            const float* kg = &K[hbase + (long)kb * BN * DH];
            #pragma unroll
            for (int it = 0; it < (BN * DH / 4) / NTHREADS; it++) {
                int i  = tid + it * NTHREADS;
                int kr = i >> 4;            // key row
                int d  = (i & 15) * 4;
                float4 f = *reinterpret_cast<const float4*>(&kg[kr * DH + d]);
                __half2* dst = reinterpret_cast<__half2*>(&sK[kr * KSTRIDE + d]);
                dst[0] = __floats2half2_rn(f.x, f.y);
                dst[1] = __floats2half2_rn(f.z, f.w);
            }
        }
        // ---- stage V tile as key-pairs: sV[k2][d] = {V[2k2][d], V[2k2+1][d]} ----
        {
            const float* vg = &V[hbase + (long)kb * BN * DH];
            #pragma unroll
            for (int it = 0; it < ((BN / 2) * (DH / 4)) / NTHREADS; it++) {
                int i  = tid + it * NTHREADS;
                int k2 = i >> 4;
                int d  = (i & 15) * 4;
                float4 fa = *reinterpret_cast<const float4*>(&vg[(2 * k2) * DH + d]);
                float4 fb = *reinterpret_cast<const float4*>(&vg[(2 * k2 + 1) * DH + d]);
                __half2* dst = &sV[k2 * VSTRIDE + d];
                dst[0] = __halves2half2(__float2half_rn(fa.x), __float2half_rn(fb.x));
                dst[1] = __halves2half2(__float2half_rn(fa.y), __float2half_rn(fb.y));
                dst[2] = __halves2half2(__float2half_rn(fa.z), __float2half_rn(fb.z));
                dst[3] = __halves2half2(__float2half_rn(fa.w), __float2half_rn(fb.w));
            }
        }
        // ---- stage additive mask ----
        if (tid < BN) {
            float mval = Mk[(long)bb * Sn + kb * BN + tid];
            sAM[tid] = -1000.0f * (1.0f - mval);
        }
        __syncthreads();

        // ---- S = (Q/8) @ K^T  [16 x 64 per warp] ----
        float s[8][4];
        #pragma unroll
        for (int n = 0; n < 8; n++)
            #pragma unroll
            for (int j = 0; j < 4; j++) s[n][j] = 0.0f;

        #pragma unroll
        for (int kc = 0; kc < 4; kc++) {
            #pragma unroll
            for (int n = 0; n < 8; n++) {
                const __half* kp = &sK[(n * 8 + g) * KSTRIDE + kc * 16 + t2];
                uint32_t b0 = *reinterpret_cast<const uint32_t*>(kp);
                uint32_t b1 = *reinterpret_cast<const uint32_t*>(kp + 8);
                mma16816(s[n], qa[kc], b0, b1);
            }
        }

        // ---- mask + online softmax ----
        float mx1 = -INFINITY, mx2 = -INFINITY;
        #pragma unroll
        for (int n = 0; n < 8; n++) {
            float2 am = *reinterpret_cast<const float2*>(&sAM[n * 8 + t2]);
            s[n][0] += am.x; s[n][1] += am.y;
            s[n][2] += am.x; s[n][3] += am.y;
            mx1 = fmaxf(mx1, fmaxf(s[n][0], s[n][1]));
            mx2 = fmaxf(mx2, fmaxf(s[n][2], s[n][3]));
        }
        mx1 = fmaxf(mx1, __shfl_xor_sync(0xffffffffu, mx1, 1));
        mx1 = fmaxf(mx1, __shfl_xor_sync(0xffffffffu, mx1, 2));
        mx2 = fmaxf(mx2, __shfl_xor_sync(0xffffffffu, mx2, 1));
        mx2 = fmaxf(mx2, __shfl_xor_sync(0xffffffffu, mx2, 2));

        float mn1 = fmaxf(m1, mx1), mn2 = fmaxf(m2, mx2);
        float a1 = __expf(m1 - mn1), a2 = __expf(m2 - mn2);
        m1 = mn1; m2 = mn2;

        float rs1 = 0.0f, rs2 = 0.0f;
        #pragma unroll
        for (int n = 0; n < 8; n++) {
            s[n][0] = __expf(s[n][0] - m1);
            s[n][1] = __expf(s[n][1] - m1);
            s[n][2] = __expf(s[n][2] - m2);
            s[n][3] = __expf(s[n][3] - m2);
            rs1 += s[n][0] + s[n][1];
            rs2 += s[n][2] + s[n][3];
        }
        rs1 += __shfl_xor_sync(0xffffffffu, rs1, 1);
        rs1 += __shfl_xor_sync(0xffffffffu, rs1, 2);
        rs2 += __shfl_xor_sync(0xffffffffu, rs2, 1);
        rs2 += __shfl_xor_sync(0xffffffffu, rs2, 2);
        l1 = l1 * a1 + rs1;
        l2 = l2 * a2 + rs2;

        #pragma unroll
        for (int dn = 0; dn < 8; dn++) {
            oacc[dn][0] *= a1; oacc[dn][1] *= a1;
            oacc[dn][2] *= a2; oacc[dn][3] *= a2;
        }

        // ---- O += P @ V  (P from S fragments; C-layout == A-layout) ----
        #pragma unroll
        for (int kc2 = 0; kc2 < 4; kc2++) {
            uint32_t pa[4];
            pa[0] = h2bits(__floats2half2_rn(s[2 * kc2][0],     s[2 * kc2][1]));
            pa[1] = h2bits(__floats2half2_rn(s[2 * kc2][2],     s[2 * kc2][3]));
            pa[2] = h2bits(__floats2half2_rn(s[2 * kc2 + 1][0], s[2 * kc2 + 1][1]));
            pa[3] = h2bits(__floats2half2_rn(s[2 * kc2 + 1][2], s[2 * kc2 + 1][3]));
            int r = kc2 * 8 + m4;  // V key-pair row for b0
            #pragma unroll
            for (int dn = 0; dn < 8; dn++) {
                uint32_t b0 = *reinterpret_cast<const uint32_t*>(&sV[r * VSTRIDE + dn * 8 + g]);
                uint32_t b1 = *reinterpret_cast<const uint32_t*>(&sV[(r + 4) * VSTRIDE + dn * 8 + g]);
                mma16816(oacc[dn], pa, b0, b1);
            }
        }
    }

    // ---- epilogue: O / l ----
    float inv1 = 1.0f / l1, inv2 = 1.0f / l2;
    const long obase1 = hbase + (long)(qrow0 + g) * DH;
    const long obase2 = hbase + (long)(qrow0 + g + 8) * DH;
    #pragma unroll
    for (int dn = 0; dn < 8; dn++) {
        int col = dn * 8 + t2;
        float2 o1 = make_float2(oacc[dn][0] * inv1, oacc[dn][1] * inv1);
        float2 o2 = make_float2(oacc[dn][2] * inv2, oacc[dn][3] * inv2);
        *reinterpret_cast<float2*>(&O[obase1 + col]) = o1;
        *reinterpret_cast<float2*>(&O[obase2 + col]) = o2;
    }
}

extern "C" void kernel_launch(void* const* d_in, const int* in_sizes, int n_in,
                              void* d_out, int out_size) {
    const float* Q  = (const float*)d_in[0];
    const float* K  = (const float*)d_in[1];
    const float* V  = (const float*)d_in[2];
    const float* Mk = (const float*)d_in[3];
    float* O = (float*)d_out;

    const int Sn = 2048;
    const int bh_total = in_sizes[0] / (Sn * DH);      // B*H = 64
    const int Bn = in_sizes[3] / Sn;                   // 4
    const int Hn = bh_total / Bn;                      // 16

    dim3 grid(Sn / BM, bh_total);
    dim3 block(NTHREADS);
    attn_flash_f16<<<grid, block>>>(Q, K, V, Mk, O, Hn, Sn);
}